// round 15
// baseline (speedup 1.0000x reference)
#include <cuda_runtime.h>

#define NEGV (-1e30f)

__device__ __forceinline__ float4 fmax4(float4 a, float4 b) {
    a.x = fmaxf(a.x, b.x);
    a.y = fmaxf(a.y, b.y);
    a.z = fmaxf(a.z, b.z);
    a.w = fmaxf(a.w, b.w);
    return a;
}

// One block (128 threads = 4 warps) per (b,l) token (best-measured config):
//   warp 0: left  path, d[  0:128)
//   warp 1: left  path, d[128:256)
//   warp 2: right path, d[  0:128)
//   warp 3: right path, d[128:256)
// 32-reg cap -> 16 blocks/SM -> 64 warps/SM theoretical occupancy.
// Lane p holds paths[token][p] (P == 32); index broadcast is a shfl on
// register state only, so unroll-4 keeps ~4 gather LDG.128 in flight.
// NEW vs R9: output stores use __stwt (STG .cs, evict-first) — the output
// is write-once/never-read, so keep it from polluting L2 ways that the
// gathered input rows (the latency-critical traffic) want to occupy.
__global__ __launch_bounds__(128, 16) void path_max_kernel(
    const float* __restrict__ inputs,   // [B,L,D] f32, D=256
    const int*   __restrict__ lpaths,   // [B,L,P]
    const int*   __restrict__ rpaths,   // [B,L,P]
    const int*   __restrict__ llens,    // [B,L]
    const int*   __restrict__ rlens,    // [B,L]
    const int*   __restrict__ slens,    // [B]
    float*       __restrict__ out)      // [B,L,2D]
{
    constexpr int L = 512, P = 32;

    const int token = blockIdx.x;
    const int warp  = threadIdx.x >> 5;
    const int lane  = threadIdx.x & 31;
    const int side  = warp >> 1;     // 0 = left, 1 = right
    const int half  = warp & 1;      // 0 = d[0:128), 1 = d[128:256)
    const int b     = token >> 9;    // token / L
    const int l     = token & (L - 1);

    // Output quadrant: token row has 512 floats = 128 float4.
    float4* o4 = reinterpret_cast<float4*>(out)
               + (size_t)token * 128 + side * 64 + half * 32 + lane;

    if (l >= __ldg(&slens[b])) {
        __stwt(o4, make_float4(0.f, 0.f, 0.f, 0.f));
        return;
    }

    const int* __restrict__ paths = side ? rpaths : lpaths;
    const int len = side ? __ldg(&rlens[token]) : __ldg(&llens[token]);
    const int my  = __ldg(&paths[(size_t)token * P + lane]);

    // Each row of inputs[b] is 64 float4; this warp reads float4 column
    // (half*32 + lane) of each gathered row -> coalesced 512B per LDG.128.
    const float4* __restrict__ base =
        reinterpret_cast<const float4*>(inputs)
        + (size_t)b * L * 64 + half * 32 + lane;

    float4 m = make_float4(NEGV, NEGV, NEGV, NEGV);

    int idx = __shfl_sync(0xffffffffu, my, 0);
    #pragma unroll 4
    for (int p = 0; p < len; ++p) {
        const float4 v = __ldg(base + (size_t)idx * 64);
        idx = __shfl_sync(0xffffffffu, my, (p + 1) & 31);  // independent of v
        m = fmax4(m, v);
    }

    __stwt(o4, m);
}

extern "C" void kernel_launch(void* const* d_in, const int* in_sizes, int n_in,
                              void* d_out, int out_size) {
    const float* inputs = (const float*)d_in[0];
    const int*   lpaths = (const int*)d_in[1];
    const int*   rpaths = (const int*)d_in[2];
    const int*   llens  = (const int*)d_in[3];
    const int*   rlens  = (const int*)d_in[4];
    const int*   slens  = (const int*)d_in[5];

    const int B = in_sizes[5];      // sent_lens has B elements
    const int tokens = B * 512;     // one block per token

    path_max_kernel<<<tokens, 128>>>(inputs, lpaths, rpaths,
                                     llens, rlens, slens,
                                     (float*)d_out);
}